// round 4
// baseline (speedup 1.0000x reference)
#include <cuda_runtime.h>
#include <cuda_bf16.h>
#include <cstdint>

#define TOKENS   16384
#define HIDDEN   4096
#define EXPERTS  64

#define M_TILE   128
#define KC       64
#define NITER    (HIDDEN / KC)     // 64
#define NTHREADS 256

// ---- shared memory layout (bytes from dynamic smem base) ----
#define SM_SCALES 64
#define A_TILE_BYTES (M_TILE * 128)          // 16384 (128 rows x 128B = 64 bf16)
#define B_TILE_BYTES (EXPERTS * 128)         // 8192
#define SM_AHI    1024
#define SM_ALO    (SM_AHI + 2 * A_TILE_BYTES)   // 33792
#define SM_B      (SM_ALO + 2 * A_TILE_BYTES)   // 66560
#define SM_TOTAL  (SM_B + 2 * B_TILE_BYTES)     // 82944

// SW128 swizzle (Swizzle<3,4,3>)
#define SW(o) ((o) ^ (((o) >> 3) & 0x70))

// dequantized weights: int8 values are EXACT in bf16; scale folded into epilogue
__device__ __nv_bfloat16 g_wb[EXPERTS * HIDDEN];

// ---------------- helpers ----------------
__device__ __forceinline__ uint32_t smem_to_u32(const void* p) {
    uint32_t a;
    asm("{ .reg .u64 t; cvta.to.shared.u64 t, %1; cvt.u32.u64 %0, t; }" : "=r"(a) : "l"(p));
    return a;
}

__device__ __forceinline__ void sts128(uint32_t addr, uint32_t a, uint32_t b,
                                       uint32_t c, uint32_t d) {
    asm volatile("st.shared.v4.b32 [%0], {%1,%2,%3,%4};"
                 :: "r"(addr), "r"(a), "r"(b), "r"(c), "r"(d) : "memory");
}

// pack_bf16(lo, hi): low half-word = bf16(lo), high = bf16(hi)
__device__ __forceinline__ uint32_t pack_bf16(float lo, float hi) {
    uint32_t r;
    asm("cvt.rn.bf16x2.f32 %0, %1, %2;" : "=r"(r) : "f"(hi), "f"(lo));
    return r;
}
__device__ __forceinline__ float bf_lo(uint32_t p) { return __uint_as_float(p << 16); }
__device__ __forceinline__ float bf_hi(uint32_t p) { return __uint_as_float(p & 0xffff0000u); }

__device__ __forceinline__ void ldsm4(uint32_t (&r)[4], uint32_t addr) {
    asm volatile("ldmatrix.sync.aligned.m8n8.x4.shared.b16 {%0,%1,%2,%3}, [%4];"
                 : "=r"(r[0]), "=r"(r[1]), "=r"(r[2]), "=r"(r[3]) : "r"(addr));
}

__device__ __forceinline__ void mma16816(float (&d)[4], const uint32_t (&a)[4],
                                         uint32_t b0, uint32_t b1) {
    asm volatile("mma.sync.aligned.m16n8k16.row.col.f32.bf16.bf16.f32 "
                 "{%0,%1,%2,%3}, {%4,%5,%6,%7}, {%8,%9}, {%0,%1,%2,%3};"
                 : "+f"(d[0]), "+f"(d[1]), "+f"(d[2]), "+f"(d[3])
                 : "r"(a[0]), "r"(a[1]), "r"(a[2]), "r"(a[3]), "r"(b0), "r"(b1));
}

// ---------------- kernels ----------------

__global__ void dequant_kernel(const int* __restrict__ w) {
    int t = blockIdx.x * blockDim.x + threadIdx.x;        // 0..65535
    int4 v = ((const int4*)w)[t];
    __nv_bfloat162 p0 = __floats2bfloat162_rn((float)v.x, (float)v.y);
    __nv_bfloat162 p1 = __floats2bfloat162_rn((float)v.z, (float)v.w);
    ((__nv_bfloat162*)g_wb)[2 * t]     = p0;
    ((__nv_bfloat162*)g_wb)[2 * t + 1] = p1;
}

__global__ void __launch_bounds__(NTHREADS, 1)
gemm_kernel(const float* __restrict__ x,
            const float* __restrict__ scales,
            float* __restrict__ out) {
    extern __shared__ char smem[];
    const uint32_t sbase = smem_to_u32(smem);
    const int tid = threadIdx.x;
    const int wid = tid >> 5;
    const int lid = tid & 31;
    const int m0  = blockIdx.x * M_TILE;

    if (tid < EXPERTS) ((float*)(smem + SM_SCALES))[tid] = scales[tid];
    __syncthreads();

    // ---- producer mapping: thread -> (rows r0 & r0+64 of A tile / expert r0 of B,
    //                                   16-element quarter q of the 64-wide chunk)
    const int r0 = tid >> 2;   // 0..63
    const int q  = tid & 3;    // 0..3
    const float* xp0 = x + (size_t)(m0 + r0) * HIDDEN + q * 16;
    const float* xp1 = xp0 + (size_t)64 * HIDDEN;
    const __nv_bfloat16* wp = g_wb + (size_t)r0 * HIDDEN + q * 16;

    const uint32_t oA0 = (uint32_t)r0 * 128 + q * 32;   // byte offset within tile
    const uint32_t oA1 = oA0 + 64 * 128;

    // ---- consumer mapping (per warp): rows 16*wid .. 16*wid+15, all 64 experts
    const uint32_t aOff = (uint32_t)(16 * wid + (lid & 15)) * 128 + (uint32_t)(lid >> 4) * 16;
    const uint32_t bOff = (uint32_t)((lid & 7) + ((lid >> 4) << 3)) * 128
                        + (uint32_t)((lid >> 3) & 1) * 16;

    float acc[8][4];
#pragma unroll
    for (int n = 0; n < 8; n++)
#pragma unroll
        for (int j = 0; j < 4; j++) acc[n][j] = 0.0f;

    // ---- 2-deep register prefetch: ping-pong sets an[s]/bn[s]
    float4 an[2][8]; uint4 bn[2][2];
#pragma unroll
    for (int s = 0; s < 2; s++) {
        const float4* p0 = (const float4*)(xp0 + s * KC);
        const float4* p1 = (const float4*)(xp1 + s * KC);
        an[s][0] = p0[0]; an[s][1] = p0[1]; an[s][2] = p0[2]; an[s][3] = p0[3];
        an[s][4] = p1[0]; an[s][5] = p1[1]; an[s][6] = p1[2]; an[s][7] = p1[3];
        const uint4* pb = (const uint4*)(wp + s * KC);
        bn[s][0] = pb[0]; bn[s][1] = pb[1];
    }

#pragma unroll 1
    for (int i = 0; i < NITER; i++) {
        const int b = i & 1;
        const uint32_t hiB = sbase + SM_AHI + b * A_TILE_BYTES;
        const uint32_t loB = sbase + SM_ALO + b * A_TILE_BYTES;
        const uint32_t bB  = sbase + SM_B   + b * B_TILE_BYTES;

        // ---- convert chunk i (register set b) to hi/lo bf16 and store to SMEM
#pragma unroll
        for (int h = 0; h < 2; h++) {
            uint32_t hh[8], ll[8];
#pragma unroll
            for (int j = 0; j < 4; j++) {
                float4 f = an[b][h * 4 + j];
                uint32_t h0 = pack_bf16(f.x, f.y);
                uint32_t h1 = pack_bf16(f.z, f.w);
                float lx = f.x - bf_lo(h0);
                float ly = f.y - bf_hi(h0);
                float lz = f.z - bf_lo(h1);
                float lw = f.w - bf_hi(h1);
                hh[2 * j] = h0; hh[2 * j + 1] = h1;
                ll[2 * j] = pack_bf16(lx, ly);
                ll[2 * j + 1] = pack_bf16(lz, lw);
            }
            uint32_t o = h ? oA1 : oA0;
            sts128(hiB + SW(o),      hh[0], hh[1], hh[2], hh[3]);
            sts128(hiB + SW(o + 16), hh[4], hh[5], hh[6], hh[7]);
            sts128(loB + SW(o),      ll[0], ll[1], ll[2], ll[3]);
            sts128(loB + SW(o + 16), ll[4], ll[5], ll[6], ll[7]);
        }
        sts128(bB + SW(oA0),      bn[b][0].x, bn[b][0].y, bn[b][0].z, bn[b][0].w);
        sts128(bB + SW(oA0 + 16), bn[b][1].x, bn[b][1].y, bn[b][1].z, bn[b][1].w);

        // ---- prefetch chunk i+2 into register set b (covers ~1.3 iterations)
        if (i + 2 < NITER) {
            const float4* p0 = (const float4*)(xp0 + (i + 2) * KC);
            const float4* p1 = (const float4*)(xp1 + (i + 2) * KC);
            an[b][0] = p0[0]; an[b][1] = p0[1]; an[b][2] = p0[2]; an[b][3] = p0[3];
            an[b][4] = p1[0]; an[b][5] = p1[1]; an[b][6] = p1[2]; an[b][7] = p1[3];
            const uint4* pb = (const uint4*)(wp + (i + 2) * KC);
            bn[b][0] = pb[0]; bn[b][1] = pb[1];
        }

        __syncthreads();   // buffer b full; prior-iter MMA reads of buffer b all precede this

        // ---- consume buffer b: 4 k-steps of 16, 8 n-tiles, hi+lo
#pragma unroll
        for (int ks = 0; ks < 4; ks++) {
            uint32_t ah[4], al[4];
            ldsm4(ah, hiB + SW(aOff + ks * 32));
            ldsm4(al, loB + SW(aOff + ks * 32));
#pragma unroll
            for (int np = 0; np < 4; np++) {
                uint32_t bb[4];
                ldsm4(bb, bB + SW(bOff + np * 16 * 128 + ks * 32));
                mma16816(acc[2 * np],     ah, bb[0], bb[1]);
                mma16816(acc[2 * np + 1], ah, bb[2], bb[3]);
                mma16816(acc[2 * np],     al, bb[0], bb[1]);
                mma16816(acc[2 * np + 1], al, bb[2], bb[3]);
            }
        }
    }

    // ---- epilogue: apply per-expert scales, write fp32
    const float* sc = (const float*)(smem + SM_SCALES);
    const int rbase = m0 + 16 * wid + (lid >> 2);
    const int cq = 2 * (lid & 3);
#pragma unroll
    for (int nt = 0; nt < 8; nt++) {
        const int c0 = 8 * nt + cq;
        const float s0 = sc[c0], s1 = sc[c0 + 1];
        float2 v0 = make_float2(acc[nt][0] * s0, acc[nt][1] * s1);
        float2 v1 = make_float2(acc[nt][2] * s0, acc[nt][3] * s1);
        *(float2*)(out + (size_t)rbase * EXPERTS + c0)       = v0;
        *(float2*)(out + (size_t)(rbase + 8) * EXPERTS + c0) = v1;
    }
}

extern "C" void kernel_launch(void* const* d_in, const int* in_sizes, int n_in,
                              void* d_out, int out_size) {
    const float* x      = (const float*)d_in[0];
    const int*   w      = (const int*)d_in[1];
    const float* scales = (const float*)d_in[2];
    float* out = (float*)d_out;

    cudaFuncSetAttribute(gemm_kernel, cudaFuncAttributeMaxDynamicSharedMemorySize, SM_TOTAL);

    dequant_kernel<<<256, 256>>>(w);                                  // 64*4096 int32 -> bf16
    gemm_kernel<<<TOKENS / M_TILE, NTHREADS, SM_TOTAL>>>(x, scales, out);
}

// round 5
// speedup vs baseline: 1.5854x; 1.5854x over previous
#include <cuda_runtime.h>
#include <cuda_bf16.h>
#include <cstdint>

#define TOKENS   16384
#define HIDDEN   4096
#define EXPERTS  64

#define M_TILE   128
#define KC       64
#define NITER    (HIDDEN / KC)     // 64
#define NTHREADS 256

// ---- shared memory layout (bytes from dynamic smem base) ----
#define SM_SCALES 64
#define A_TILE_BYTES (M_TILE * 128)          // 16384 (128 rows x 128B = 64 bf16)
#define B_TILE_BYTES (EXPERTS * 128)         // 8192
#define SM_AHI    1024
#define SM_ALO    (SM_AHI + 2 * A_TILE_BYTES)   // 33792
#define SM_B      (SM_ALO + 2 * A_TILE_BYTES)   // 66560
#define SM_TOTAL  (SM_B + 2 * B_TILE_BYTES)     // 82944

// SW128 swizzle (Swizzle<3,4,3>)
#define SW(o) ((o) ^ (((o) >> 3) & 0x70))

// dequantized weights: int8 values are EXACT in bf16; scale folded into epilogue
__device__ __nv_bfloat16 g_wb[EXPERTS * HIDDEN];

// ---------------- helpers ----------------
__device__ __forceinline__ uint32_t smem_to_u32(const void* p) {
    uint32_t a;
    asm("{ .reg .u64 t; cvta.to.shared.u64 t, %1; cvt.u32.u64 %0, t; }" : "=r"(a) : "l"(p));
    return a;
}

__device__ __forceinline__ void sts128(uint32_t addr, uint32_t a, uint32_t b,
                                       uint32_t c, uint32_t d) {
    asm volatile("st.shared.v4.b32 [%0], {%1,%2,%3,%4};"
                 :: "r"(addr), "r"(a), "r"(b), "r"(c), "r"(d) : "memory");
}

// pack_bf16(lo, hi): low half-word = bf16(lo), high = bf16(hi)
__device__ __forceinline__ uint32_t pack_bf16(float lo, float hi) {
    uint32_t r;
    asm("cvt.rn.bf16x2.f32 %0, %1, %2;" : "=r"(r) : "f"(hi), "f"(lo));
    return r;
}
__device__ __forceinline__ float bf_lo(uint32_t p) { return __uint_as_float(p << 16); }
__device__ __forceinline__ float bf_hi(uint32_t p) { return __uint_as_float(p & 0xffff0000u); }

__device__ __forceinline__ void ldsm4(uint32_t (&r)[4], uint32_t addr) {
    asm volatile("ldmatrix.sync.aligned.m8n8.x4.shared.b16 {%0,%1,%2,%3}, [%4];"
                 : "=r"(r[0]), "=r"(r[1]), "=r"(r[2]), "=r"(r[3]) : "r"(addr));
}

__device__ __forceinline__ void mma16816(float (&d)[4], const uint32_t (&a)[4],
                                         uint32_t b0, uint32_t b1) {
    asm volatile("mma.sync.aligned.m16n8k16.row.col.f32.bf16.bf16.f32 "
                 "{%0,%1,%2,%3}, {%4,%5,%6,%7}, {%8,%9}, {%0,%1,%2,%3};"
                 : "+f"(d[0]), "+f"(d[1]), "+f"(d[2]), "+f"(d[3])
                 : "r"(a[0]), "r"(a[1]), "r"(a[2]), "r"(a[3]), "r"(b0), "r"(b1));
}

// ---------------- kernels ----------------

__global__ void dequant_kernel(const int* __restrict__ w) {
    int t = blockIdx.x * blockDim.x + threadIdx.x;        // 0..65535
    int4 v = ((const int4*)w)[t];
    __nv_bfloat162 p0 = __floats2bfloat162_rn((float)v.x, (float)v.y);
    __nv_bfloat162 p1 = __floats2bfloat162_rn((float)v.z, (float)v.w);
    ((__nv_bfloat162*)g_wb)[2 * t]     = p0;
    ((__nv_bfloat162*)g_wb)[2 * t + 1] = p1;
}

struct Ctx {
    const float* xp0; const float* xp1; const __nv_bfloat16* wp;
    uint32_t oA0, oA1, aOff, bOff, sbase;
};

// convert register chunk -> hi/lo bf16 SMEM tiles + B tile
__device__ __forceinline__ void stage(const Ctx& c, const float4 (&a)[8],
                                      const uint4 (&bw)[2],
                                      uint32_t hiB, uint32_t loB, uint32_t bB) {
#pragma unroll
    for (int h = 0; h < 2; h++) {
        uint32_t hh[8], ll[8];
#pragma unroll
        for (int j = 0; j < 4; j++) {
            float4 f = a[h * 4 + j];
            uint32_t h0 = pack_bf16(f.x, f.y);
            uint32_t h1 = pack_bf16(f.z, f.w);
            float lx = f.x - bf_lo(h0);
            float ly = f.y - bf_hi(h0);
            float lz = f.z - bf_lo(h1);
            float lw = f.w - bf_hi(h1);
            hh[2 * j] = h0; hh[2 * j + 1] = h1;
            ll[2 * j] = pack_bf16(lx, ly);
            ll[2 * j + 1] = pack_bf16(lz, lw);
        }
        uint32_t o = h ? c.oA1 : c.oA0;
        sts128(hiB + SW(o),      hh[0], hh[1], hh[2], hh[3]);
        sts128(hiB + SW(o + 16), hh[4], hh[5], hh[6], hh[7]);
        sts128(loB + SW(o),      ll[0], ll[1], ll[2], ll[3]);
        sts128(loB + SW(o + 16), ll[4], ll[5], ll[6], ll[7]);
    }
    sts128(bB + SW(c.oA0),      bw[0].x, bw[0].y, bw[0].z, bw[0].w);
    sts128(bB + SW(c.oA0 + 16), bw[1].x, bw[1].y, bw[1].z, bw[1].w);
}

__device__ __forceinline__ void prefetch(const Ctx& c, int chunk,
                                         float4 (&a)[8], uint4 (&bw)[2]) {
    const float4* p0 = (const float4*)(c.xp0 + chunk * KC);
    const float4* p1 = (const float4*)(c.xp1 + chunk * KC);
    a[0] = p0[0]; a[1] = p0[1]; a[2] = p0[2]; a[3] = p0[3];
    a[4] = p1[0]; a[5] = p1[1]; a[6] = p1[2]; a[7] = p1[3];
    const uint4* pb = (const uint4*)(c.wp + chunk * KC);
    bw[0] = pb[0]; bw[1] = pb[1];
}

__device__ __forceinline__ void consume(const Ctx& c, float (&acc)[8][4],
                                        uint32_t hiB, uint32_t loB, uint32_t bB) {
#pragma unroll
    for (int ks = 0; ks < 4; ks++) {
        uint32_t ah[4], al[4];
        ldsm4(ah, hiB + SW(c.aOff + ks * 32));
        ldsm4(al, loB + SW(c.aOff + ks * 32));
#pragma unroll
        for (int np = 0; np < 4; np++) {
            uint32_t bb[4];
            ldsm4(bb, bB + SW(c.bOff + np * 16 * 128 + ks * 32));
            mma16816(acc[2 * np],     ah, bb[0], bb[1]);
            mma16816(acc[2 * np + 1], ah, bb[2], bb[3]);
            mma16816(acc[2 * np],     al, bb[0], bb[1]);
            mma16816(acc[2 * np + 1], al, bb[2], bb[3]);
        }
    }
}

__global__ void __launch_bounds__(NTHREADS, 1)
gemm_kernel(const float* __restrict__ x,
            const float* __restrict__ scales,
            float* __restrict__ out) {
    extern __shared__ char smem[];
    const uint32_t sbase = smem_to_u32(smem);
    const int tid = threadIdx.x;
    const int wid = tid >> 5;
    const int lid = tid & 31;
    const int m0  = blockIdx.x * M_TILE;

    if (tid < EXPERTS) ((float*)(smem + SM_SCALES))[tid] = scales[tid];
    __syncthreads();

    // producer mapping: thread -> (rows r0 & r0+64 of A / expert r0 of B, quarter q)
    const int r0 = tid >> 2;   // 0..63
    const int q  = tid & 3;    // 0..3

    Ctx c;
    c.xp0 = x + (size_t)(m0 + r0) * HIDDEN + q * 16;
    c.xp1 = c.xp0 + (size_t)64 * HIDDEN;
    c.wp  = g_wb + (size_t)r0 * HIDDEN + q * 16;
    c.oA0 = (uint32_t)r0 * 128 + q * 32;
    c.oA1 = c.oA0 + 64 * 128;
    c.aOff = (uint32_t)(16 * wid + (lid & 15)) * 128 + (uint32_t)(lid >> 4) * 16;
    c.bOff = (uint32_t)((lid & 7) + ((lid >> 4) << 3)) * 128
           + (uint32_t)((lid >> 3) & 1) * 16;
    c.sbase = sbase;

    const uint32_t hi0 = sbase + SM_AHI,               hi1 = hi0 + A_TILE_BYTES;
    const uint32_t lo0 = sbase + SM_ALO,               lo1 = lo0 + A_TILE_BYTES;
    const uint32_t b0  = sbase + SM_B,                 b1  = b0 + B_TILE_BYTES;

    float acc[8][4];
#pragma unroll
    for (int n = 0; n < 8; n++)
#pragma unroll
        for (int j = 0; j < 4; j++) acc[n][j] = 0.0f;

    // ---- 2-deep register prefetch; STATIC set indices only (no spills)
    float4 a0[8], a1[8]; uint4 w0[2], w1[2];
    prefetch(c, 0, a0, w0);
    prefetch(c, 1, a1, w1);

#pragma unroll 1
    for (int i = 0; i < NITER; i += 2) {
        // ---- sub-iter A: stage set0 -> buffer0, prefetch chunk i+2 -> set0
        stage(c, a0, w0, hi0, lo0, b0);
        if (i + 2 < NITER) prefetch(c, i + 2, a0, w0);
        __syncthreads();                 // buffer0 full (WAR vs prev consume: OK, separated by last sync)
        consume(c, acc, hi0, lo0, b0);

        // ---- sub-iter B: stage set1 -> buffer1, prefetch chunk i+3 -> set1
        stage(c, a1, w1, hi1, lo1, b1);
        if (i + 3 < NITER) prefetch(c, i + 3, a1, w1);
        __syncthreads();                 // buffer1 full
        consume(c, acc, hi1, lo1, b1);
    }

    // ---- epilogue: apply per-expert scales, write fp32
    const float* sc = (const float*)(smem + SM_SCALES);
    const int rbase = m0 + 16 * wid + (lid >> 2);
    const int cq = 2 * (lid & 3);
#pragma unroll
    for (int nt = 0; nt < 8; nt++) {
        const int c0 = 8 * nt + cq;
        const float s0 = sc[c0], s1 = sc[c0 + 1];
        float2 v0 = make_float2(acc[nt][0] * s0, acc[nt][1] * s1);
        float2 v1 = make_float2(acc[nt][2] * s0, acc[nt][3] * s1);
        *(float2*)(out + (size_t)rbase * EXPERTS + c0)       = v0;
        *(float2*)(out + (size_t)(rbase + 8) * EXPERTS + c0) = v1;
    }
}

extern "C" void kernel_launch(void* const* d_in, const int* in_sizes, int n_in,
                              void* d_out, int out_size) {
    const float* x      = (const float*)d_in[0];
    const int*   w      = (const int*)d_in[1];
    const float* scales = (const float*)d_in[2];
    float* out = (float*)d_out;

    cudaFuncSetAttribute(gemm_kernel, cudaFuncAttributeMaxDynamicSharedMemorySize, SM_TOTAL);

    dequant_kernel<<<256, 256>>>(w);                                  // 64*4096 int32 -> bf16
    gemm_kernel<<<TOKENS / M_TILE, NTHREADS, SM_TOTAL>>>(x, scales, out);
}

// round 6
// speedup vs baseline: 1.6143x; 1.0182x over previous
#include <cuda_runtime.h>
#include <cuda_bf16.h>
#include <cstdint>

#define TOKENS   16384
#define HIDDEN   4096
#define EXPERTS  64

#define M_TILE   128
#define KC       64
#define NITER    (HIDDEN / KC)     // 64
#define NTHREADS 512

// ---- shared memory layout (bytes from dynamic smem base) ----
#define SM_SCALES 64
#define A_TILE_BYTES (M_TILE * 128)          // 16384 (128 rows x 128B = 64 bf16)
#define B_TILE_BYTES (EXPERTS * 128)         // 8192
#define SM_AHI    1024
#define SM_ALO    (SM_AHI + 2 * A_TILE_BYTES)   // 33792
#define SM_B      (SM_ALO + 2 * A_TILE_BYTES)   // 66560
#define SM_TOTAL  (SM_B + 2 * B_TILE_BYTES)     // 82944

// SW128 swizzle (Swizzle<3,4,3>)
#define SW(o) ((o) ^ (((o) >> 3) & 0x70))

// dequantized weights: int8 values are EXACT in bf16; scale folded into epilogue
__device__ __nv_bfloat16 g_wb[EXPERTS * HIDDEN];

// ---------------- helpers ----------------
__device__ __forceinline__ uint32_t smem_to_u32(const void* p) {
    uint32_t a;
    asm("{ .reg .u64 t; cvta.to.shared.u64 t, %1; cvt.u32.u64 %0, t; }" : "=r"(a) : "l"(p));
    return a;
}

__device__ __forceinline__ void sts128(uint32_t addr, uint32_t a, uint32_t b,
                                       uint32_t c, uint32_t d) {
    asm volatile("st.shared.v4.b32 [%0], {%1,%2,%3,%4};"
                 :: "r"(addr), "r"(a), "r"(b), "r"(c), "r"(d) : "memory");
}

// pack_bf16(lo, hi): low half-word = bf16(lo), high = bf16(hi)
__device__ __forceinline__ uint32_t pack_bf16(float lo, float hi) {
    uint32_t r;
    asm("cvt.rn.bf16x2.f32 %0, %1, %2;" : "=r"(r) : "f"(hi), "f"(lo));
    return r;
}
__device__ __forceinline__ float bf_lo(uint32_t p) { return __uint_as_float(p << 16); }
__device__ __forceinline__ float bf_hi(uint32_t p) { return __uint_as_float(p & 0xffff0000u); }

__device__ __forceinline__ void ldsm4(uint32_t (&r)[4], uint32_t addr) {
    asm volatile("ldmatrix.sync.aligned.m8n8.x4.shared.b16 {%0,%1,%2,%3}, [%4];"
                 : "=r"(r[0]), "=r"(r[1]), "=r"(r[2]), "=r"(r[3]) : "r"(addr));
}

__device__ __forceinline__ void mma16816(float (&d)[4], const uint32_t (&a)[4],
                                         uint32_t b0, uint32_t b1) {
    asm volatile("mma.sync.aligned.m16n8k16.row.col.f32.bf16.bf16.f32 "
                 "{%0,%1,%2,%3}, {%4,%5,%6,%7}, {%8,%9}, {%0,%1,%2,%3};"
                 : "+f"(d[0]), "+f"(d[1]), "+f"(d[2]), "+f"(d[3])
                 : "r"(a[0]), "r"(a[1]), "r"(a[2]), "r"(a[3]), "r"(b0), "r"(b1));
}

// ---------------- kernels ----------------

__global__ void dequant_kernel(const int* __restrict__ w) {
    int t = blockIdx.x * blockDim.x + threadIdx.x;        // 0..65535
    int4 v = ((const int4*)w)[t];
    __nv_bfloat162 p0 = __floats2bfloat162_rn((float)v.x, (float)v.y);
    __nv_bfloat162 p1 = __floats2bfloat162_rn((float)v.z, (float)v.w);
    ((__nv_bfloat162*)g_wb)[2 * t]     = p0;
    ((__nv_bfloat162*)g_wb)[2 * t + 1] = p1;
}

__global__ void __launch_bounds__(NTHREADS, 1)
gemm_kernel(const float* __restrict__ x,
            const float* __restrict__ scales,
            float* __restrict__ out) {
    extern __shared__ char smem[];
    const uint32_t sbase = smem_to_u32(smem);
    const int tid = threadIdx.x;
    const int wid = tid >> 5;
    const int lid = tid & 31;
    const int m0  = blockIdx.x * M_TILE;

    if (tid < EXPERTS) ((float*)(smem + SM_SCALES))[tid] = scales[tid];
    __syncthreads();

    // ---- producer mapping (512 threads):
    //   A: thread -> row r0 (0..127), 16-float quarter q of the 64-float chunk row
    //   B: thread -> expert e (0..63), 8-bf16 octet o
    const int r0 = tid >> 2;                 // 0..127
    const int q  = tid & 3;                  // 0..3
    const float* xp = x + (size_t)(m0 + r0) * HIDDEN + q * 16;
    const uint32_t oA = (uint32_t)r0 * 128 + q * 32;   // 32 bytes of bf16 per thread

    const int e = tid >> 3;                  // 0..63
    const int o = tid & 7;                   // 0..7
    const __nv_bfloat16* wp = g_wb + (size_t)e * HIDDEN + o * 8;
    const uint32_t oB = (uint32_t)e * 128 + o * 16;    // 16 bytes per thread

    // ---- consumer mapping (16 warps): rows 16*(wid&7), experts 32*(wid>>3)
    const int wm = wid & 7;
    const int cg = wid >> 3;
    const uint32_t aOff = (uint32_t)(16 * wm + (lid & 15)) * 128 + (uint32_t)(lid >> 4) * 16;
    const uint32_t bOff = (uint32_t)(32 * cg + (lid & 7) + ((lid >> 4) << 3)) * 128
                        + (uint32_t)((lid >> 3) & 1) * 16;

    float acc[4][4];
#pragma unroll
    for (int n = 0; n < 4; n++)
#pragma unroll
        for (int j = 0; j < 4; j++) acc[n][j] = 0.0f;

    // 1-deep register prefetch: chunk 0
    float4 an[4]; uint4 bn;
    {
        const float4* p = (const float4*)xp;
        an[0] = p[0]; an[1] = p[1]; an[2] = p[2]; an[3] = p[3];
        bn = *(const uint4*)wp;
    }

#pragma unroll 1
    for (int i = 0; i < NITER; i++) {
        const int b = i & 1;
        const uint32_t hiB = sbase + SM_AHI + b * A_TILE_BYTES;
        const uint32_t loB = sbase + SM_ALO + b * A_TILE_BYTES;
        const uint32_t bB  = sbase + SM_B   + b * B_TILE_BYTES;

        // ---- stage: convert 16 floats -> 16 bf16 hi + 16 bf16 lo, store + B
        {
            uint32_t hh[8], ll[8];
#pragma unroll
            for (int j = 0; j < 4; j++) {
                float4 f = an[j];
                uint32_t h0 = pack_bf16(f.x, f.y);
                uint32_t h1 = pack_bf16(f.z, f.w);
                float lx = f.x - bf_lo(h0);
                float ly = f.y - bf_hi(h0);
                float lz = f.z - bf_lo(h1);
                float lw = f.w - bf_hi(h1);
                hh[2 * j] = h0; hh[2 * j + 1] = h1;
                ll[2 * j] = pack_bf16(lx, ly);
                ll[2 * j + 1] = pack_bf16(lz, lw);
            }
            sts128(hiB + SW(oA),      hh[0], hh[1], hh[2], hh[3]);
            sts128(hiB + SW(oA + 16), hh[4], hh[5], hh[6], hh[7]);
            sts128(loB + SW(oA),      ll[0], ll[1], ll[2], ll[3]);
            sts128(loB + SW(oA + 16), ll[4], ll[5], ll[6], ll[7]);
            sts128(bB + SW(oB), bn.x, bn.y, bn.z, bn.w);
        }

        // ---- prefetch chunk i+1 (LDG lands during the consume phase)
        if (i + 1 < NITER) {
            const float4* p = (const float4*)(xp + (i + 1) * KC);
            an[0] = p[0]; an[1] = p[1]; an[2] = p[2]; an[3] = p[3];
            bn = *(const uint4*)(wp + (i + 1) * KC);
        }

        __syncthreads();   // buffer b full; prior consume of buffer b precedes (2 syncs ago)

        // ---- consume: 4 k-steps, 2 expert-16-tiles, hi+lo
#pragma unroll
        for (int ks = 0; ks < 4; ks++) {
            uint32_t ah[4], al[4];
            ldsm4(ah, hiB + SW(aOff + ks * 32));
            ldsm4(al, loB + SW(aOff + ks * 32));
#pragma unroll
            for (int np = 0; np < 2; np++) {
                uint32_t bb[4];
                ldsm4(bb, bB + SW(bOff + np * 16 * 128 + ks * 32));
                mma16816(acc[2 * np],     ah, bb[0], bb[1]);
                mma16816(acc[2 * np + 1], ah, bb[2], bb[3]);
                mma16816(acc[2 * np],     al, bb[0], bb[1]);
                mma16816(acc[2 * np + 1], al, bb[2], bb[3]);
            }
        }
    }

    // ---- epilogue: apply per-expert scales, write fp32
    const float* sc = (const float*)(smem + SM_SCALES);
    const int rbase = m0 + 16 * wm + (lid >> 2);
    const int cq = 32 * cg + 2 * (lid & 3);
#pragma unroll
    for (int nt = 0; nt < 4; nt++) {
        const int c0 = cq + 8 * nt;
        const float s0 = sc[c0], s1 = sc[c0 + 1];
        float2 v0 = make_float2(acc[nt][0] * s0, acc[nt][1] * s1);
        float2 v1 = make_float2(acc[nt][2] * s0, acc[nt][3] * s1);
        *(float2*)(out + (size_t)rbase * EXPERTS + c0)       = v0;
        *(float2*)(out + (size_t)(rbase + 8) * EXPERTS + c0) = v1;
    }
}

extern "C" void kernel_launch(void* const* d_in, const int* in_sizes, int n_in,
                              void* d_out, int out_size) {
    const float* x      = (const float*)d_in[0];
    const int*   w      = (const int*)d_in[1];
    const float* scales = (const float*)d_in[2];
    float* out = (float*)d_out;

    cudaFuncSetAttribute(gemm_kernel, cudaFuncAttributeMaxDynamicSharedMemorySize, SM_TOTAL);

    dequant_kernel<<<256, 256>>>(w);                                  // 64*4096 int32 -> bf16
    gemm_kernel<<<TOKENS / M_TILE, NTHREADS, SM_TOTAL>>>(x, scales, out);
}

// round 7
// speedup vs baseline: 2.1126x; 1.3087x over previous
#include <cuda_runtime.h>
#include <cuda_bf16.h>
#include <cstdint>

#define TOKENS   16384
#define HIDDEN   4096
#define EXPERTS  64

#define M_TILE   128
#define KC       64
#define NITER    (HIDDEN / KC)     // 64
#define NTHREADS 512

// ---- shared memory layout (bytes from dynamic smem base) ----
#define SM_SCALES 64
#define A_TILE_BYTES (M_TILE * 128)          // 16384 (128 rows x 128B = 64 bf16)
#define B_TILE_BYTES (EXPERTS * 128)         // 8192
#define SM_AHI    1024
#define SM_ALO    (SM_AHI + 2 * A_TILE_BYTES)   // 33792
#define SM_B      (SM_ALO + 2 * A_TILE_BYTES)   // 66560
#define SM_TOTAL  (SM_B + 2 * B_TILE_BYTES)     // 82944

// SW128 swizzle (Swizzle<3,4,3>)
#define SW(o) ((o) ^ (((o) >> 3) & 0x70))

// dequantized weights: int8 values are EXACT in bf16; scale folded into epilogue
__device__ __nv_bfloat16 g_wb[EXPERTS * HIDDEN];

// ---------------- helpers ----------------
__device__ __forceinline__ uint32_t smem_to_u32(const void* p) {
    uint32_t a;
    asm("{ .reg .u64 t; cvta.to.shared.u64 t, %1; cvt.u32.u64 %0, t; }" : "=r"(a) : "l"(p));
    return a;
}

__device__ __forceinline__ void sts128(uint32_t addr, uint32_t a, uint32_t b,
                                       uint32_t c, uint32_t d) {
    asm volatile("st.shared.v4.b32 [%0], {%1,%2,%3,%4};"
                 :: "r"(addr), "r"(a), "r"(b), "r"(c), "r"(d) : "memory");
}

__device__ __forceinline__ void sts64(uint32_t addr, uint32_t a, uint32_t b) {
    asm volatile("st.shared.v2.b32 [%0], {%1,%2};"
                 :: "r"(addr), "r"(a), "r"(b) : "memory");
}

// pack_bf16(lo, hi): low half-word = bf16(lo), high = bf16(hi)
__device__ __forceinline__ uint32_t pack_bf16(float lo, float hi) {
    uint32_t r;
    asm("cvt.rn.bf16x2.f32 %0, %1, %2;" : "=r"(r) : "f"(hi), "f"(lo));
    return r;
}
__device__ __forceinline__ float bf_lo(uint32_t p) { return __uint_as_float(p << 16); }
__device__ __forceinline__ float bf_hi(uint32_t p) { return __uint_as_float(p & 0xffff0000u); }

__device__ __forceinline__ void ldsm4(uint32_t (&r)[4], uint32_t addr) {
    asm volatile("ldmatrix.sync.aligned.m8n8.x4.shared.b16 {%0,%1,%2,%3}, [%4];"
                 : "=r"(r[0]), "=r"(r[1]), "=r"(r[2]), "=r"(r[3]) : "r"(addr));
}

__device__ __forceinline__ void mma16816(float (&d)[4], const uint32_t (&a)[4],
                                         uint32_t b0, uint32_t b1) {
    asm volatile("mma.sync.aligned.m16n8k16.row.col.f32.bf16.bf16.f32 "
                 "{%0,%1,%2,%3}, {%4,%5,%6,%7}, {%8,%9}, {%0,%1,%2,%3};"
                 : "+f"(d[0]), "+f"(d[1]), "+f"(d[2]), "+f"(d[3])
                 : "r"(a[0]), "r"(a[1]), "r"(a[2]), "r"(a[3]), "r"(b0), "r"(b1));
}

// ---------------- kernels ----------------

__global__ void dequant_kernel(const int* __restrict__ w) {
    int t = blockIdx.x * blockDim.x + threadIdx.x;        // 0..65535
    int4 v = ((const int4*)w)[t];
    __nv_bfloat162 p0 = __floats2bfloat162_rn((float)v.x, (float)v.y);
    __nv_bfloat162 p1 = __floats2bfloat162_rn((float)v.z, (float)v.w);
    ((__nv_bfloat162*)g_wb)[2 * t]     = p0;
    ((__nv_bfloat162*)g_wb)[2 * t + 1] = p1;
}

__global__ void __launch_bounds__(NTHREADS, 1)
gemm_kernel(const float* __restrict__ x,
            const float* __restrict__ scales,
            float* __restrict__ out) {
    extern __shared__ char smem[];
    const uint32_t sbase = smem_to_u32(smem);
    const int tid = threadIdx.x;
    const int wid = tid >> 5;
    const int lid = tid & 31;
    const int m0  = blockIdx.x * M_TILE;

    if (tid < EXPERTS) ((float*)(smem + SM_SCALES))[tid] = scales[tid];
    __syncthreads();

    // ---- producer mapping, A: warp w stages rows 8w..8w+7.
    //   LDG instruction j covers rows (8w+2j, 8w+2j+1): thread -> row 8w+2j+(lid>>4),
    //   16B piece (lid&15) of that row's 256B chunk  => 4 cache lines per LDG.128.
    const int lsub = lid >> 4;          // 0..1
    const int lcol = lid & 15;          // 0..15 (16B units)
    const float* xA = x + (size_t)(m0 + 8 * wid + lsub) * HIDDEN + lcol * 4;
    uint32_t oAr[4];
#pragma unroll
    for (int j = 0; j < 4; j++)
        oAr[j] = (uint32_t)(8 * wid + 2 * j + lsub) * 128 + lcol * 8;  // bf16 tile offsets

    // ---- producer mapping, B: thread -> expert e (0..63), 8-bf16 octet o (coalesced)
    const int e = tid >> 3;                  // 0..63
    const int o = tid & 7;                   // 0..7
    const __nv_bfloat16* wp = g_wb + (size_t)e * HIDDEN + o * 8;
    const uint32_t oB = (uint32_t)e * 128 + o * 16;

    // ---- consumer mapping (16 warps): rows 16*(wid&7), experts 32*(wid>>3)
    const int wm = wid & 7;
    const int cg = wid >> 3;
    const uint32_t aOff = (uint32_t)(16 * wm + (lid & 15)) * 128 + (uint32_t)(lid >> 4) * 16;
    const uint32_t bOff = (uint32_t)(32 * cg + (lid & 7) + ((lid >> 4) << 3)) * 128
                        + (uint32_t)((lid >> 3) & 1) * 16;

    float acc[4][4];
#pragma unroll
    for (int n = 0; n < 4; n++)
#pragma unroll
        for (int j = 0; j < 4; j++) acc[n][j] = 0.0f;

    // 1-deep register prefetch: chunk 0
    float4 an[4]; uint4 bn;
#pragma unroll
    for (int j = 0; j < 4; j++)
        an[j] = *(const float4*)(xA + (size_t)(2 * j) * HIDDEN);
    bn = *(const uint4*)wp;

#pragma unroll 1
    for (int i = 0; i < NITER; i++) {
        const int b = i & 1;
        const uint32_t hiB = sbase + SM_AHI + b * A_TILE_BYTES;
        const uint32_t loB = sbase + SM_ALO + b * A_TILE_BYTES;
        const uint32_t bB  = sbase + SM_B   + b * B_TILE_BYTES;

        // ---- stage: each float4 (one row piece) -> 8B hi + 8B lo
#pragma unroll
        for (int j = 0; j < 4; j++) {
            float4 f = an[j];
            uint32_t h0 = pack_bf16(f.x, f.y);
            uint32_t h1 = pack_bf16(f.z, f.w);
            float lx = f.x - bf_lo(h0);
            float ly = f.y - bf_hi(h0);
            float lz = f.z - bf_lo(h1);
            float lw = f.w - bf_hi(h1);
            uint32_t l0 = pack_bf16(lx, ly);
            uint32_t l1 = pack_bf16(lz, lw);
            sts64(hiB + SW(oAr[j]), h0, h1);
            sts64(loB + SW(oAr[j]), l0, l1);
        }
        sts128(bB + SW(oB), bn.x, bn.y, bn.z, bn.w);

        // ---- prefetch chunk i+1 (lands during the consume phase)
        if (i + 1 < NITER) {
#pragma unroll
            for (int j = 0; j < 4; j++)
                an[j] = *(const float4*)(xA + (size_t)(2 * j) * HIDDEN + (i + 1) * KC);
            bn = *(const uint4*)(wp + (i + 1) * KC);
        }

        __syncthreads();   // buffer b full; prior consume of buffer b was 2 syncs ago

        // ---- consume: 4 k-steps, 2 expert-16-tiles, hi+lo
#pragma unroll
        for (int ks = 0; ks < 4; ks++) {
            uint32_t ah[4], al[4];
            ldsm4(ah, hiB + SW(aOff + ks * 32));
            ldsm4(al, loB + SW(aOff + ks * 32));
#pragma unroll
            for (int np = 0; np < 2; np++) {
                uint32_t bb[4];
                ldsm4(bb, bB + SW(bOff + np * 16 * 128 + ks * 32));
                mma16816(acc[2 * np],     ah, bb[0], bb[1]);
                mma16816(acc[2 * np + 1], ah, bb[2], bb[3]);
                mma16816(acc[2 * np],     al, bb[0], bb[1]);
                mma16816(acc[2 * np + 1], al, bb[2], bb[3]);
            }
        }
    }

    // ---- epilogue: apply per-expert scales, write fp32
    const float* sc = (const float*)(smem + SM_SCALES);
    const int rbase = m0 + 16 * wm + (lid >> 2);
    const int cq = 32 * cg + 2 * (lid & 3);
#pragma unroll
    for (int nt = 0; nt < 4; nt++) {
        const int c0 = cq + 8 * nt;
        const float s0 = sc[c0], s1 = sc[c0 + 1];
        float2 v0 = make_float2(acc[nt][0] * s0, acc[nt][1] * s1);
        float2 v1 = make_float2(acc[nt][2] * s0, acc[nt][3] * s1);
        *(float2*)(out + (size_t)rbase * EXPERTS + c0)       = v0;
        *(float2*)(out + (size_t)(rbase + 8) * EXPERTS + c0) = v1;
    }
}

extern "C" void kernel_launch(void* const* d_in, const int* in_sizes, int n_in,
                              void* d_out, int out_size) {
    const float* x      = (const float*)d_in[0];
    const int*   w      = (const int*)d_in[1];
    const float* scales = (const float*)d_in[2];
    float* out = (float*)d_out;

    cudaFuncSetAttribute(gemm_kernel, cudaFuncAttributeMaxDynamicSharedMemorySize, SM_TOTAL);

    dequant_kernel<<<256, 256>>>(w);                                  // 64*4096 int32 -> bf16
    gemm_kernel<<<TOKENS / M_TILE, NTHREADS, SM_TOTAL>>>(x, scales, out);
}

// round 8
// speedup vs baseline: 2.2943x; 1.0860x over previous
#include <cuda_runtime.h>
#include <cuda_bf16.h>
#include <cstdint>

#define TOKENS   16384
#define HIDDEN   4096
#define EXPERTS  64

#define M_TILE   128
#define KC       64
#define NITER    (HIDDEN / KC)     // 64
#define NTHREADS 512

// ---- shared memory layout (bytes from dynamic smem base) ----
#define SM_SCALES 64
#define A_TILE_BYTES (M_TILE * 128)          // 16384 (128 rows x 128B = 64 bf16)
#define B_TILE_BYTES (EXPERTS * 128)         // 8192
#define SM_AHI    1024
#define SM_ALO    (SM_AHI + 2 * A_TILE_BYTES)   // 33792
#define SM_B      (SM_ALO + 2 * A_TILE_BYTES)   // 66560
#define SM_RED    (SM_B + 2 * B_TILE_BYTES)     // 82944 (32KB reduction buffer)
#define SM_TOTAL  (SM_RED + 32768)              // 115712

// SW128 swizzle (Swizzle<3,4,3>)
#define SW(o) ((o) ^ (((o) >> 3) & 0x70))

// dequantized weights: int8 values are EXACT in bf16; scale folded into epilogue
__device__ __nv_bfloat16 g_wb[EXPERTS * HIDDEN];

// ---------------- helpers ----------------
__device__ __forceinline__ uint32_t smem_to_u32(const void* p) {
    uint32_t a;
    asm("{ .reg .u64 t; cvta.to.shared.u64 t, %1; cvt.u32.u64 %0, t; }" : "=r"(a) : "l"(p));
    return a;
}

__device__ __forceinline__ void sts128(uint32_t addr, uint32_t a, uint32_t b,
                                       uint32_t c, uint32_t d) {
    asm volatile("st.shared.v4.b32 [%0], {%1,%2,%3,%4};"
                 :: "r"(addr), "r"(a), "r"(b), "r"(c), "r"(d) : "memory");
}

__device__ __forceinline__ void sts64(uint32_t addr, uint32_t a, uint32_t b) {
    asm volatile("st.shared.v2.b32 [%0], {%1,%2};"
                 :: "r"(addr), "r"(a), "r"(b) : "memory");
}

__device__ __forceinline__ void lds128f(float (&v)[4], uint32_t addr) {
    asm volatile("ld.shared.v4.f32 {%0,%1,%2,%3}, [%4];"
                 : "=f"(v[0]), "=f"(v[1]), "=f"(v[2]), "=f"(v[3]) : "r"(addr));
}

// pack_bf16(lo, hi): low half-word = bf16(lo), high = bf16(hi)
__device__ __forceinline__ uint32_t pack_bf16(float lo, float hi) {
    uint32_t r;
    asm("cvt.rn.bf16x2.f32 %0, %1, %2;" : "=r"(r) : "f"(hi), "f"(lo));
    return r;
}
__device__ __forceinline__ float bf_lo(uint32_t p) { return __uint_as_float(p << 16); }
__device__ __forceinline__ float bf_hi(uint32_t p) { return __uint_as_float(p & 0xffff0000u); }

__device__ __forceinline__ void ldsm4(uint32_t (&r)[4], uint32_t addr) {
    asm volatile("ldmatrix.sync.aligned.m8n8.x4.shared.b16 {%0,%1,%2,%3}, [%4];"
                 : "=r"(r[0]), "=r"(r[1]), "=r"(r[2]), "=r"(r[3]) : "r"(addr));
}

__device__ __forceinline__ void mma16816(float (&d)[4], const uint32_t (&a)[4],
                                         uint32_t b0, uint32_t b1) {
    asm volatile("mma.sync.aligned.m16n8k16.row.col.f32.bf16.bf16.f32 "
                 "{%0,%1,%2,%3}, {%4,%5,%6,%7}, {%8,%9}, {%0,%1,%2,%3};"
                 : "+f"(d[0]), "+f"(d[1]), "+f"(d[2]), "+f"(d[3])
                 : "r"(a[0]), "r"(a[1]), "r"(a[2]), "r"(a[3]), "r"(b0), "r"(b1));
}

// ---------------- kernels ----------------

__global__ void dequant_kernel(const int* __restrict__ w) {
    int t = blockIdx.x * blockDim.x + threadIdx.x;        // 0..65535
    int4 v = ((const int4*)w)[t];
    __nv_bfloat162 p0 = __floats2bfloat162_rn((float)v.x, (float)v.y);
    __nv_bfloat162 p1 = __floats2bfloat162_rn((float)v.z, (float)v.w);
    ((__nv_bfloat162*)g_wb)[2 * t]     = p0;
    ((__nv_bfloat162*)g_wb)[2 * t + 1] = p1;
}

__global__ void __launch_bounds__(NTHREADS, 1)
gemm_kernel(const float* __restrict__ x,
            const float* __restrict__ scales,
            float* __restrict__ out) {
    extern __shared__ char smem[];
    const uint32_t sbase = smem_to_u32(smem);
    const int tid = threadIdx.x;
    const int wid = tid >> 5;
    const int lid = tid & 31;
    const int m0  = blockIdx.x * M_TILE;

    if (tid < EXPERTS) ((float*)(smem + SM_SCALES))[tid] = scales[tid];
    __syncthreads();

    // ---- producer mapping, A (as R7): warp w stages rows 8w..8w+7.
    //   LDG j covers rows (8w+2j, 8w+2j+1): thread -> row 8w+2j+(lid>>4),
    //   16B piece (lid&15) of that row's 256B chunk  => 4 cache lines per LDG.128.
    const int lsub = lid >> 4;          // 0..1
    const int lcol = lid & 15;          // 0..15 (16B units)
    const float* xA = x + (size_t)(m0 + 8 * wid + lsub) * HIDDEN + lcol * 4;
    uint32_t oAr[4];
#pragma unroll
    for (int j = 0; j < 4; j++)
        oAr[j] = (uint32_t)(8 * wid + 2 * j + lsub) * 128 + lcol * 8;

    // ---- producer mapping, B: thread -> expert e (0..63), 8-bf16 octet o
    const int e = tid >> 3;
    const int o = tid & 7;
    const __nv_bfloat16* wp = g_wb + (size_t)e * HIDDEN + o * 8;
    const uint32_t oB = (uint32_t)e * 128 + o * 16;

    // ---- consumer mapping (16 warps): 4 row-groups x 4 k-split groups
    //   warp = 32 rows (2 m-tiles) x 64 experts (8 n-tiles) x 16-wide k-slice
    const int rg = wid & 3;             // row group: rows 32*rg..32*rg+31
    const int kg = wid >> 2;            // k-split: k bytes [32*kg, 32*kg+32)
    const uint32_t aOffBase = (uint32_t)(32 * rg + (lid & 15)) * 128
                            + (uint32_t)kg * 32 + (uint32_t)(lid >> 4) * 16;
    const uint32_t bOffBase = (uint32_t)((lid & 7) + ((lid >> 4) << 3)) * 128
                            + (uint32_t)kg * 32 + (uint32_t)((lid >> 3) & 1) * 16;

    float acc[2][8][4];
#pragma unroll
    for (int mt = 0; mt < 2; mt++)
#pragma unroll
        for (int nt = 0; nt < 8; nt++)
#pragma unroll
            for (int j = 0; j < 4; j++) acc[mt][nt][j] = 0.0f;

    // 1-deep register prefetch: chunk 0
    float4 an[4]; uint4 bn;
#pragma unroll
    for (int j = 0; j < 4; j++)
        an[j] = *(const float4*)(xA + (size_t)(2 * j) * HIDDEN);
    bn = *(const uint4*)wp;

#pragma unroll 1
    for (int i = 0; i < NITER; i++) {
        const int b = i & 1;
        const uint32_t hiB = sbase + SM_AHI + b * A_TILE_BYTES;
        const uint32_t loB = sbase + SM_ALO + b * A_TILE_BYTES;
        const uint32_t bB  = sbase + SM_B   + b * B_TILE_BYTES;

        // ---- stage: each float4 (one row piece) -> 8B hi + 8B lo
#pragma unroll
        for (int j = 0; j < 4; j++) {
            float4 f = an[j];
            uint32_t h0 = pack_bf16(f.x, f.y);
            uint32_t h1 = pack_bf16(f.z, f.w);
            float lx = f.x - bf_lo(h0);
            float ly = f.y - bf_hi(h0);
            float lz = f.z - bf_lo(h1);
            float lw = f.w - bf_hi(h1);
            uint32_t l0 = pack_bf16(lx, ly);
            uint32_t l1 = pack_bf16(lz, lw);
            sts64(hiB + SW(oAr[j]), h0, h1);
            sts64(loB + SW(oAr[j]), l0, l1);
        }
        sts128(bB + SW(oB), bn.x, bn.y, bn.z, bn.w);

        // ---- prefetch chunk i+1 (lands during the consume phase)
        if (i + 1 < NITER) {
#pragma unroll
            for (int j = 0; j < 4; j++)
                an[j] = *(const float4*)(xA + (size_t)(2 * j) * HIDDEN + (i + 1) * KC);
            bn = *(const uint4*)(wp + (i + 1) * KC);
        }

        __syncthreads();   // buffer b full; prior consume of buffer b was 2 syncs ago

        // ---- consume: this warp's 16-wide k-slice only
        uint32_t bb[4][4];
#pragma unroll
        for (int bp = 0; bp < 4; bp++)
            ldsm4(bb[bp], bB + SW(bOffBase + (uint32_t)bp * 16 * 128));

#pragma unroll
        for (int mt = 0; mt < 2; mt++) {
            uint32_t ah[4], al[4];
            ldsm4(ah, hiB + SW(aOffBase + (uint32_t)mt * 16 * 128));
            ldsm4(al, loB + SW(aOffBase + (uint32_t)mt * 16 * 128));
#pragma unroll
            for (int bp = 0; bp < 4; bp++) {
                mma16816(acc[mt][2 * bp],     ah, bb[bp][0], bb[bp][1]);
                mma16816(acc[mt][2 * bp + 1], ah, bb[bp][2], bb[bp][3]);
                mma16816(acc[mt][2 * bp],     al, bb[bp][0], bb[bp][1]);
                mma16816(acc[mt][2 * bp + 1], al, bb[bp][2], bb[bp][3]);
            }
        }
    }

    // ---- k-split reduction: kg 1..3 fold into kg 0 via 32KB smem buffer
    const uint32_t redW = sbase + SM_RED + (uint32_t)rg * 8192;
#pragma unroll 1
    for (int r = 1; r < 4; r++) {
        if (kg == r) {
#pragma unroll
            for (int mt = 0; mt < 2; mt++)
#pragma unroll
                for (int nt = 0; nt < 8; nt++)
                    sts128(redW + (uint32_t)(mt * 8 + nt) * 512 + (uint32_t)lid * 16,
                           __float_as_uint(acc[mt][nt][0]), __float_as_uint(acc[mt][nt][1]),
                           __float_as_uint(acc[mt][nt][2]), __float_as_uint(acc[mt][nt][3]));
        }
        __syncthreads();
        if (kg == 0) {
#pragma unroll
            for (int mt = 0; mt < 2; mt++)
#pragma unroll
                for (int nt = 0; nt < 8; nt++) {
                    float v[4];
                    lds128f(v, redW + (uint32_t)(mt * 8 + nt) * 512 + (uint32_t)lid * 16);
                    acc[mt][nt][0] += v[0]; acc[mt][nt][1] += v[1];
                    acc[mt][nt][2] += v[2]; acc[mt][nt][3] += v[3];
                }
        }
        __syncthreads();
    }

    // ---- epilogue (kg 0 warps only): apply per-expert scales, write fp32
    if (kg == 0) {
        const float* sc = (const float*)(smem + SM_SCALES);
        const int cq = 2 * (lid & 3);
#pragma unroll
        for (int mt = 0; mt < 2; mt++) {
            const int rbase = m0 + 32 * rg + 16 * mt + (lid >> 2);
#pragma unroll
            for (int nt = 0; nt < 8; nt++) {
                const int c0 = 8 * nt + cq;
                const float s0 = sc[c0], s1 = sc[c0 + 1];
                float2 v0 = make_float2(acc[mt][nt][0] * s0, acc[mt][nt][1] * s1);
                float2 v1 = make_float2(acc[mt][nt][2] * s0, acc[mt][nt][3] * s1);
                *(float2*)(out + (size_t)rbase * EXPERTS + c0)       = v0;
                *(float2*)(out + (size_t)(rbase + 8) * EXPERTS + c0) = v1;
            }
        }
    }
}

extern "C" void kernel_launch(void* const* d_in, const int* in_sizes, int n_in,
                              void* d_out, int out_size) {
    const float* x      = (const float*)d_in[0];
    const int*   w      = (const int*)d_in[1];
    const float* scales = (const float*)d_in[2];
    float* out = (float*)d_out;

    cudaFuncSetAttribute(gemm_kernel, cudaFuncAttributeMaxDynamicSharedMemorySize, SM_TOTAL);

    dequant_kernel<<<256, 256>>>(w);                                  // 64*4096 int32 -> bf16
    gemm_kernel<<<TOKENS / M_TILE, NTHREADS, SM_TOTAL>>>(x, scales, out);
}